// round 9
// baseline (speedup 1.0000x reference)
#include <cuda_runtime.h>
#include <cstdint>

#define HW    3136
#define CIN   1024
#define NT    112      // 28 * 112 = 3136 exactly
#define KC    32
#define NCH   8

// per-CTA smem (floats): A: 2 buffers of 4 kk-octets x 128 m x 8 (swizzled)
//                        B: 2 buffers of [32 k][pitch 120]
#define ASZ     4096
#define BOFF    (2 * ASZ)             // 8192
#define BPITCH  120
#define BSZ     (KC * BPITCH)         // 3840
#define SM_FLOATS (BOFF + 2 * BSZ)    // 15872
#define SM_BYTES  (SM_FLOATS * 4)     // 63488 -> two CTAs fit in 228KB

static __device__ __forceinline__ float rna_f(float v) {
    uint32_t o;
    asm("cvt.rna.tf32.f32 %0, %1;" : "=r"(o) : "f"(v));
    return __uint_as_float(o);
}
static __device__ __forceinline__ uint32_t smem_u32(const void* p) {
    uint32_t a;
    asm("{\n\t.reg .u64 t;\n\tcvta.to.shared.u64 t, %1;\n\tcvt.u32.u64 %0, t;\n\t}"
        : "=r"(a) : "l"(p));
    return a;
}
static __device__ __forceinline__ void cp16(uint32_t dst, const void* src) {
    asm volatile("cp.async.cg.shared.global [%0], [%1], 16;" :: "r"(dst), "l"(src) : "memory");
}
static __device__ __forceinline__ void cp_commit() {
    asm volatile("cp.async.commit_group;" ::: "memory");
}
static __device__ __forceinline__ void cp_wait0() {
    asm volatile("cp.async.wait_group 0;" ::: "memory");
}

static __device__ __forceinline__ void mma8(float* c, const float* a, const float* b) {
    asm volatile(
        "mma.sync.aligned.m16n8k8.row.col.f32.tf32.tf32.f32 "
        "{%0,%1,%2,%3}, {%4,%5,%6,%7}, {%8,%9}, {%0,%1,%2,%3};"
        : "+f"(c[0]), "+f"(c[1]), "+f"(c[2]), "+f"(c[3])
        : "r"(__float_as_uint(a[0])), "r"(__float_as_uint(a[1])),
          "r"(__float_as_uint(a[2])), "r"(__float_as_uint(a[3])),
          "r"(__float_as_uint(b[0])), "r"(__float_as_uint(b[1])));
}

__global__ __launch_bounds__(128, 2)
void scc_mma_kernel(const float* __restrict__ x,
                    const float* __restrict__ w,
                    float* __restrict__ out)
{
    extern __shared__ float sm[];
    const uint32_t sb = smem_u32(sm);
    const int tid = threadIdx.x;
    const int lid = tid & 31, wid = tid >> 5;       // 4 warps
    const int g = lid >> 2, tg = lid & 3;
    const int r  = blockIdx.x;                      // group fastest: L2 x reuse
    const int p0 = blockIdx.y * NT;
    const int b  = blockIdx.z;
    const float* xb = x + (size_t)b * CIN * HW;

    // warp grid 2(M) x 2(N): warp tile 64 x 56 over CTA tile 128 x 112
    const int m0 = (wid & 1) * 64;
    const int n0 = (wid >> 1) * 56;

    float acc[4][7][4];
    #pragma unroll
    for (int i = 0; i < 4; i++)
        #pragma unroll
        for (int j = 0; j < 7; j++)
            #pragma unroll
            for (int v = 0; v < 4; v++) acc[i][j][v] = 0.f;

    // ---- A loader role: one m-row per thread, all 4 k-octets of the chunk ----
    const int am = tid;                             // 0..127
    const int aswz = 2 * ((am >> 2) & 3);
    const float* wrow = w + (size_t)(r + 8 * am) * 256;
    float areg[32];

    auto LDG_A = [&](int ch) {
        #pragma unroll
        for (int o = 0; o < 4; o++) {
            *(float4*)&areg[o * 8 + 0] = *(const float4*)(wrow + ch * KC + o * 8);
            *(float4*)&areg[o * 8 + 4] = *(const float4*)(wrow + ch * KC + o * 8 + 4);
        }
    };
    auto STS_A = [&](int buf) {
        float* Ab = sm + buf * ASZ;
        #pragma unroll
        for (int o = 0; o < 4; o++) {
            float* dst = Ab + o * 1024 + am * 8;
            #pragma unroll
            for (int c = 0; c < 4; c++)
                *(float2*)(dst + ((2 * c) ^ aswz)) =
                    make_float2(rna_f(areg[o * 8 + c]), rna_f(areg[o * 8 + c + 4]));
        }
    };
    // ---- B loader: 7 x 16B cp.async per chunk; idx = tid+128*it -> k=idx/28, nq=idx%28
    auto CPA_B = [&](int ch, int buf) {
        const int c0 = (r * 128 + ch * KC) & (CIN - 1);
        const uint32_t bbase = sb + (BOFF + buf * BSZ) * 4;
        #pragma unroll
        for (int it = 0; it < 7; it++) {
            const int idx = tid + 128 * it;
            const int k = idx / 28, nq = idx % 28;
            cp16(bbase + (k * BPITCH + 4 * nq) * 4,
                 xb + (size_t)(c0 + k) * HW + p0 + 4 * nq);
        }
        cp_commit();
    };

    auto COMPUTE = [&](int buf) {
        const float* Ab = sm + buf * ASZ;
        const float* Bb = sm + BOFF + buf * BSZ;
        #pragma unroll
        for (int kk = 0; kk < 4; kk++) {
            const float* Abk = Ab + kk * 1024;
            const float* Bbk = Bb + kk * 8 * BPITCH;
            float af[4][4], bf[7][2];
            #pragma unroll
            for (int i = 0; i < 4; i++) {
                const int rlo = m0 + 16 * i + g;
                const int rhi = rlo + 8;
                const float2 lo = *(const float2*)(Abk + rlo * 8 + ((2 * tg) ^ (2 * ((rlo >> 2) & 3))));
                const float2 hi = *(const float2*)(Abk + rhi * 8 + ((2 * tg) ^ (2 * ((rhi >> 2) & 3))));
                af[i][0] = lo.x; af[i][1] = hi.x; af[i][2] = lo.y; af[i][3] = hi.y;
            }
            #pragma unroll
            for (int j = 0; j < 7; j++) {
                const int n = n0 + 8 * j + g;
                bf[j][0] = Bbk[tg * BPITCH + n];
                bf[j][1] = Bbk[(tg + 4) * BPITCH + n];
            }
            #pragma unroll
            for (int i = 0; i < 4; i++)
                #pragma unroll
                for (int j = 0; j < 7; j++)
                    mma8(acc[i][j], af[i], bf[j]);
        }
    };

    // ---- pipelined mainloop (R5 structure) ----
    CPA_B(0, 0);
    LDG_A(0);
    STS_A(0);
    cp_wait0();
    __syncthreads();

    #pragma unroll 1
    for (int ch = 0; ch < NCH; ch++) {
        const int buf = ch & 1;
        if (ch + 1 < NCH) {
            CPA_B(ch + 1, buf ^ 1);   // async into other buffer, overlaps compute
            LDG_A(ch + 1);
        }
        COMPUTE(buf);
        if (ch + 1 < NCH) {
            STS_A(buf ^ 1);
            cp_wait0();
            __syncthreads();
        }
    }

    // ---- epilogue: direct STG, float2 halves (full 32B sectors across quads) ----
    float* ob = out + ((size_t)b * 1024 + r) * HW + p0 + n0 + 2 * tg;
    #pragma unroll
    for (int i = 0; i < 4; i++) {
        const int mlo = m0 + 16 * i + g;
        float* prow = ob + (size_t)(8 * mlo) * HW;
        #pragma unroll
        for (int j = 0; j < 7; j++) {
            *(float2*)(prow + 8 * j) = make_float2(acc[i][j][0], acc[i][j][1]);
            *(float2*)(prow + (size_t)64 * HW + 8 * j) = make_float2(acc[i][j][2], acc[i][j][3]);
        }
    }
}

extern "C" void kernel_launch(void* const* d_in, const int* in_sizes, int n_in,
                              void* d_out, int out_size)
{
    const float* x = (const float*)d_in[0];
    const float* w = (const float*)d_in[1];
    float* out = (float*)d_out;

    cudaFuncSetAttribute(scc_mma_kernel,
                         cudaFuncAttributeMaxDynamicSharedMemorySize, SM_BYTES);
    dim3 grid(8, 28, 16);   // 3584 CTAs, 2 per SM; r fastest for L2 x reuse
    scc_mma_kernel<<<grid, 128, SM_BYTES>>>(x, w, out);
}

// round 11
// speedup vs baseline: 1.1064x; 1.1064x over previous
#include <cuda_runtime.h>
#include <cstdint>

#define HW    3136
#define CIN   1024
#define NT    224      // 14 * 224 = 3136 exactly
#define KC    32
#define NCH   8

// smem (floats): A: 2 buffers of 4 kk-octets x 128 m x 8 (swizzled)
//                B: 3-stage ring of [32 k][pitch 232]
#define ASZ     4096
#define BOFF    (2 * ASZ)              // 8192
#define BPITCH  232
#define BSZ     (KC * BPITCH)          // 7424
#define NSTAGE  3
#define SM_FLOATS (BOFF + NSTAGE * BSZ) // 30464
#define SM_BYTES  (SM_FLOATS * 4)       // 121856

static __device__ __forceinline__ float rna_f(float v) {
    uint32_t o;
    asm("cvt.rna.tf32.f32 %0, %1;" : "=r"(o) : "f"(v));
    return __uint_as_float(o);
}
static __device__ __forceinline__ uint32_t smem_u32(const void* p) {
    uint32_t a;
    asm("{\n\t.reg .u64 t;\n\tcvta.to.shared.u64 t, %1;\n\tcvt.u32.u64 %0, t;\n\t}"
        : "=r"(a) : "l"(p));
    return a;
}
static __device__ __forceinline__ void cp16(uint32_t dst, const void* src) {
    asm volatile("cp.async.cg.shared.global [%0], [%1], 16;" :: "r"(dst), "l"(src) : "memory");
}
static __device__ __forceinline__ void cp_commit() {
    asm volatile("cp.async.commit_group;" ::: "memory");
}
template <int N>
static __device__ __forceinline__ void cp_wait() {
    asm volatile("cp.async.wait_group %0;" :: "n"(N) : "memory");
}

static __device__ __forceinline__ void mma8(float* c, const float* a, const float* b) {
    asm volatile(
        "mma.sync.aligned.m16n8k8.row.col.f32.tf32.tf32.f32 "
        "{%0,%1,%2,%3}, {%4,%5,%6,%7}, {%8,%9}, {%0,%1,%2,%3};"
        : "+f"(c[0]), "+f"(c[1]), "+f"(c[2]), "+f"(c[3])
        : "r"(__float_as_uint(a[0])), "r"(__float_as_uint(a[1])),
          "r"(__float_as_uint(a[2])), "r"(__float_as_uint(a[3])),
          "r"(__float_as_uint(b[0])), "r"(__float_as_uint(b[1])));
}

__global__ __launch_bounds__(256, 1)
void scc_mma_kernel(const float* __restrict__ x,
                    const float* __restrict__ w,
                    float* __restrict__ out)
{
    extern __shared__ float sm[];
    const uint32_t sb = smem_u32(sm);
    const int tid = threadIdx.x;
    const int lid = tid & 31, wid = tid >> 5;
    const int g = lid >> 2, tg = lid & 3;
    const int r  = blockIdx.x;                 // group fastest: L2 x reuse
    const int p0 = blockIdx.y * NT;
    const int b  = blockIdx.z;
    const float* xb = x + (size_t)b * CIN * HW;

    // warp grid 2(M) x 4(N): warp tile 64 x 56
    const int m0 = (wid & 1) * 64;
    const int n0 = (wid >> 1) * 56;

    float acc[4][7][4];
    #pragma unroll
    for (int i = 0; i < 4; i++)
        #pragma unroll
        for (int j = 0; j < 7; j++)
            #pragma unroll
            for (int v = 0; v < 4; v++) acc[i][j][v] = 0.f;

    // ---- A loader role: m row = tid&127, two k-octets (tid>>7)*2 + {0,1} ----
    const int am = tid & 127;
    const int ao = (tid >> 7) * 2;
    const float* wrow = w + (size_t)(r + 8 * am) * 256;
    const int aswz = 2 * ((am >> 2) & 3);
    float areg[16];

    auto LDG_A = [&](int ch) {
        #pragma unroll
        for (int o = 0; o < 2; o++) {
            *(float4*)&areg[o * 8 + 0] = *(const float4*)(wrow + ch * KC + (ao + o) * 8);
            *(float4*)&areg[o * 8 + 4] = *(const float4*)(wrow + ch * KC + (ao + o) * 8 + 4);
        }
    };
    auto STS_A = [&](int buf) {
        float* Ab = sm + buf * ASZ;
        #pragma unroll
        for (int o = 0; o < 2; o++) {
            float* dst = Ab + (ao + o) * 1024 + am * 8;
            #pragma unroll
            for (int c = 0; c < 4; c++)
                *(float2*)(dst + ((2 * c) ^ aswz)) =
                    make_float2(rna_f(areg[o * 8 + c]), rna_f(areg[o * 8 + c + 4]));
        }
    };
    // ---- B loader: 7 x 16B cp.async per chunk; idx = tid+256*it -> k=idx/56, nq=idx%56
    auto CPA_B = [&](int ch, int stage) {
        const int c0 = (r * 128 + ch * KC) & (CIN - 1);
        const uint32_t bbase = sb + (BOFF + stage * BSZ) * 4;
        #pragma unroll
        for (int it = 0; it < 7; it++) {
            const int idx = tid + 256 * it;
            const int k = idx / 56, nq = idx % 56;
            cp16(bbase + (k * BPITCH + 4 * nq) * 4,
                 xb + (size_t)(c0 + k) * HW + p0 + 4 * nq);
        }
        cp_commit();
    };

    auto COMPUTE = [&](int abuf, int stage) {
        const float* Ab = sm + abuf * ASZ;
        const float* Bb = sm + BOFF + stage * BSZ;
        #pragma unroll
        for (int kk = 0; kk < 4; kk++) {
            const float* Abk = Ab + kk * 1024;
            const float* Bbk = Bb + kk * 8 * BPITCH;
            float af[4][4], bf[7][2];
            #pragma unroll
            for (int i = 0; i < 4; i++) {
                const int rlo = m0 + 16 * i + g;
                const int rhi = rlo + 8;
                const float2 lo = *(const float2*)(Abk + rlo * 8 + ((2 * tg) ^ (2 * ((rlo >> 2) & 3))));
                const float2 hi = *(const float2*)(Abk + rhi * 8 + ((2 * tg) ^ (2 * ((rhi >> 2) & 3))));
                af[i][0] = lo.x; af[i][1] = hi.x; af[i][2] = lo.y; af[i][3] = hi.y;
            }
            #pragma unroll
            for (int j = 0; j < 7; j++) {
                const int n = n0 + 8 * j + g;
                bf[j][0] = Bbk[tg * BPITCH + n];
                bf[j][1] = Bbk[(tg + 4) * BPITCH + n];
            }
            #pragma unroll
            for (int i = 0; i < 4; i++)
                #pragma unroll
                for (int j = 0; j < 7; j++)
                    mma8(acc[i][j], af[i], bf[j]);
        }
    };

    // ---- prologue: B stages 0 and 1 in flight; A chunk 0 staged ----
    CPA_B(0, 0);
    CPA_B(1, 1);
    LDG_A(0);
    STS_A(0);
    cp_wait<1>();           // stage 0 landed, stage 1 still flying
    __syncthreads();

    // ---- mainloop: B runs 2 chunks ahead, A 1 chunk ahead ----
    #pragma unroll 1
    for (int ch = 0; ch < NCH; ch++) {
        if (ch + 2 < NCH) CPA_B(ch + 2, (ch + 2) % NSTAGE);
        if (ch + 1 < NCH) LDG_A(ch + 1);
        COMPUTE(ch & 1, ch % NSTAGE);
        if (ch + 1 < NCH) {
            STS_A((ch + 1) & 1);
            if (ch + 2 < NCH) cp_wait<1>();   // ch+1 landed; ch+2 still flying
            else              cp_wait<0>();
            __syncthreads();
        }
    }

    // ---- epilogue: direct STG, float2 halves (full 32B sectors across quads) ----
    float* ob = out + ((size_t)b * 1024 + r) * HW + p0 + n0 + 2 * tg;
    #pragma unroll
    for (int i = 0; i < 4; i++) {
        const int mlo = m0 + 16 * i + g;
        float* prow = ob + (size_t)(8 * mlo) * HW;
        #pragma unroll
        for (int j = 0; j < 7; j++) {
            *(float2*)(prow + 8 * j) = make_float2(acc[i][j][0], acc[i][j][1]);
            *(float2*)(prow + (size_t)64 * HW + 8 * j) = make_float2(acc[i][j][2], acc[i][j][3]);
        }
    }
}

extern "C" void kernel_launch(void* const* d_in, const int* in_sizes, int n_in,
                              void* d_out, int out_size)
{
    const float* x = (const float*)d_in[0];
    const float* w = (const float*)d_in[1];
    float* out = (float*)d_out;

    cudaFuncSetAttribute(scc_mma_kernel,
                         cudaFuncAttributeMaxDynamicSharedMemorySize, SM_BYTES);
    dim3 grid(8, 14, 16);   // r fastest: adjacent groups share x channels in L2
    scc_mma_kernel<<<grid, 256, SM_BYTES>>>(x, w, out);
}